// round 9
// baseline (speedup 1.0000x reference)
#include <cuda_runtime.h>

#define NN 50000
#define EE 800000
#define DD 128
#define NHH 8

// ---------------- device scratch (no allocations allowed) ----------------
__device__ __align__(16) float g_V[NN * DD];     // H @ Wv^T
__device__ __align__(16) float g_R[NN * DD];     // H @ res_w^T + res_b
__device__ __align__(16) float g_agg[NN * DD];   // aggregated messages
__device__ __align__(16) float g_Adst[NN * NHH]; // H @ (W4 W1)^T
__device__ __align__(16) float g_Asrc[NN * NHH]; // H @ (W4 W2)^T
__device__ __align__(16) float g_Wa[16 * DD];    // rows 0-7: W4@W1, rows 8-15: W4@W2
__device__ float g_c[NHH];                       // W3 . W4[h]
__device__ int   g_deg[NN];
__device__ int   g_offs[NN + 1];
__device__ int   g_cursor[NN];
__device__ int   g_srcs[EE];
__device__ float g_Pe[EE];
__device__ float g_De[EE];
__device__ __align__(16) float g_exp[EE * NHH];

// ---------------- tiny prep kernels ----------------
__global__ void k_zero(int n) {
    int i = blockIdx.x * blockDim.x + threadIdx.x;
    if (i < n) { g_deg[i] = 0; g_cursor[i] = 0; }
}

__global__ void k_prep(const float* __restrict__ W1, const float* __restrict__ W2,
                       const float* __restrict__ W3, const float* __restrict__ W4) {
    int t = blockIdx.x * 256 + threadIdx.x;   // 8 blocks x 256 = 2048
    if (t < 16 * DD) {
        int h16 = t >> 7;
        int d = t & 127;
        const float* Wsel = (h16 < 8) ? W1 : W2;
        int h = h16 & 7;
        float s = 0.f;
        for (int k = 0; k < DD; k++)
            s = fmaf(W4[h * DD + k], Wsel[k * DD + d], s);
        g_Wa[t] = s;
    }
    if (t < NHH) {
        float s = 0.f;
        for (int j = 0; j < DD; j++)
            s = fmaf(W3[j], W4[t * DD + j], s);
        g_c[t] = s;
    }
}

// edge_index is int32 (JAX x64 is disabled; jnp.int64 request silently downcasts).
__global__ void k_hist(const int* __restrict__ ei, int e, int n) {
    int i = blockIdx.x * blockDim.x + threadIdx.x;
    if (i < e) {
        int dst = ei[e + i];
        dst = min(max(dst, 0), n - 1);   // defensive clamp: never trap
        atomicAdd(&g_deg[dst], 1);
    }
}

// single-block exclusive scan of g_deg -> g_offs
__global__ void k_scan(int n) {
    __shared__ int wsum[32];
    __shared__ int carry_s;
    int tid = threadIdx.x;
    int lane = tid & 31, wid = tid >> 5;
    if (tid == 0) carry_s = 0;
    __syncthreads();
    for (int base = 0; base < n; base += 1024) {
        int i = base + tid;
        int v = (i < n) ? g_deg[i] : 0;
        int x = v;
        #pragma unroll
        for (int o = 1; o < 32; o <<= 1) {
            int y = __shfl_up_sync(0xffffffffu, x, o);
            if (lane >= o) x += y;
        }
        if (lane == 31) wsum[wid] = x;
        __syncthreads();
        if (wid == 0) {
            int w = wsum[lane];
            #pragma unroll
            for (int o = 1; o < 32; o <<= 1) {
                int y = __shfl_up_sync(0xffffffffu, w, o);
                if (lane >= o) w += y;
            }
            wsum[lane] = w;
        }
        __syncthreads();
        int incl = x + (wid > 0 ? wsum[wid - 1] : 0) + carry_s;
        if (i < n) g_offs[i + 1] = incl;
        __syncthreads();
        if (tid == 1023) carry_s = incl;
        __syncthreads();
    }
    if (tid == 0) g_offs[0] = 0;
}

__global__ void k_scatter(const int* __restrict__ ei,
                          const float* __restrict__ P, const float* __restrict__ DT,
                          int e, int n) {
    int i = blockIdx.x * blockDim.x + threadIdx.x;
    if (i < e) {
        int src = ei[i];
        int dst = ei[e + i];
        src = min(max(src, 0), n - 1);
        dst = min(max(dst, 0), n - 1);
        int p = atomicAdd(&g_cursor[dst], 1);
        int j = g_offs[dst] + p;
        if (j >= 0 && j < e) {
            g_srcs[j] = src;
            g_Pe[j] = P[i];
            g_De[j] = DT[i];
        }
    }
}

// ---------------- K-chunked 128x128 GEMM machinery (static smem <=48KB) ----------
// Chunk tile: 128 rows x 32 k-cols, smem pitch 36 floats (144B, 16B-aligned rows).
#define CPITCH 36

__device__ __forceinline__ void load_chunk(float* S, const float* __restrict__ G,
                                           int row0, int nrows, int kc) {
    int tid = threadIdx.x;
    #pragma unroll
    for (int i = 0; i < 4; i++) {
        int f = tid + i * 256;            // 1024 float4s per chunk
        int row = f >> 3, q = f & 7;
        float4 v = make_float4(0.f, 0.f, 0.f, 0.f);
        if (row0 + row < nrows)
            v = *(const float4*)(G + (size_t)(row0 + row) * DD + kc * 32 + q * 4);
        *(float4*)(S + row * CPITCH + q * 4) = v;
    }
}

__device__ __forceinline__ void gemm_chunk(const float* Hs, const float* Ws,
                                           float acc[8][8], int tx, int ty) {
    #pragma unroll
    for (int kq = 0; kq < 8; kq++) {
        float4 a[8], b[8];
        #pragma unroll
        for (int i = 0; i < 8; i++)
            a[i] = *(const float4*)(Hs + (ty + 16 * i) * CPITCH + kq * 4);
        #pragma unroll
        for (int j = 0; j < 8; j++)
            b[j] = *(const float4*)(Ws + (tx + 16 * j) * CPITCH + kq * 4);
        #pragma unroll
        for (int i = 0; i < 8; i++)
            #pragma unroll
            for (int j = 0; j < 8; j++) {
                acc[i][j] = fmaf(a[i].x, b[j].x, acc[i][j]);
                acc[i][j] = fmaf(a[i].y, b[j].y, acc[i][j]);
                acc[i][j] = fmaf(a[i].z, b[j].z, acc[i][j]);
                acc[i][j] = fmaf(a[i].w, b[j].w, acc[i][j]);
            }
    }
}

// V = H@Wv^T ; R = H@res_w^T + res_b ; Adst/Asrc = H @ Wa^T
__global__ void __launch_bounds__(256) k_nodeproj(const float* __restrict__ H,
                                                  const float* __restrict__ Wv,
                                                  const float* __restrict__ resw,
                                                  const float* __restrict__ resb, int n) {
    __shared__ float Hs[128 * CPITCH];
    __shared__ float Ws[128 * CPITCH];
    __shared__ float Was[16 * 32];
    int m0 = blockIdx.x * 128;
    int tid = threadIdx.x, tx = tid & 15, ty = tid >> 4;

    // ---- pass 1: V = H @ Wv^T ----
    {
        float acc[8][8];
        #pragma unroll
        for (int i = 0; i < 8; i++)
            #pragma unroll
            for (int j = 0; j < 8; j++) acc[i][j] = 0.f;
        for (int kc = 0; kc < 4; kc++) {
            load_chunk(Hs, H, m0, n, kc);
            load_chunk(Ws, Wv, 0, 128, kc);
            __syncthreads();
            gemm_chunk(Hs, Ws, acc, tx, ty);
            __syncthreads();
        }
        #pragma unroll
        for (int i = 0; i < 8; i++) {
            int grow = m0 + ty + 16 * i;
            if (grow < n)
                #pragma unroll
                for (int j = 0; j < 8; j++)
                    g_V[(size_t)grow * DD + tx + 16 * j] = acc[i][j];
        }
    }
    __syncthreads();

    // ---- pass 2: R = H @ res_w^T + b ; A = H @ Wa^T (folded in chunk-wise) ----
    {
        float acc[8][8];
        #pragma unroll
        for (int i = 0; i < 8; i++)
            #pragma unroll
            for (int j = 0; j < 8; j++) acc[i][j] = 0.f;
        float acc2[8];
        #pragma unroll
        for (int h = 0; h < 8; h++) acc2[h] = 0.f;
        int r = tid >> 1, half = tid & 1;

        for (int kc = 0; kc < 4; kc++) {
            load_chunk(Hs, H, m0, n, kc);
            load_chunk(Ws, resw, 0, 128, kc);
            #pragma unroll
            for (int i = 0; i < 2; i++) {
                int f = tid + i * 256;    // 512 elements
                int wr = f >> 5, k = f & 31;
                Was[wr * 32 + k] = g_Wa[wr * DD + kc * 32 + k];
            }
            __syncthreads();
            gemm_chunk(Hs, Ws, acc, tx, ty);
            // attention projection: each (r, half) pair dots H row r with 8 Wa rows
            #pragma unroll
            for (int k = 0; k < 32; k++) {
                float hv = Hs[r * CPITCH + k];
                #pragma unroll
                for (int h = 0; h < 8; h++)
                    acc2[h] = fmaf(hv, Was[(half * 8 + h) * 32 + k], acc2[h]);
            }
            __syncthreads();
        }
        #pragma unroll
        for (int i = 0; i < 8; i++) {
            int grow = m0 + ty + 16 * i;
            if (grow < n)
                #pragma unroll
                for (int j = 0; j < 8; j++) {
                    int col = tx + 16 * j;
                    g_R[(size_t)grow * DD + col] = acc[i][j] + resb[col];
                }
        }
        int grow = m0 + r;
        if (grow < n) {
            float* dp = half ? (g_Asrc + (size_t)grow * 8) : (g_Adst + (size_t)grow * 8);
            #pragma unroll
            for (int h = 0; h < 8; h++) dp[h] = acc2[h];
        }
    }
}

// ---------------- per-dst-node attention + aggregation (one warp per node) --------
__global__ void __launch_bounds__(256) k_attn(int n) {
    int gw = (int)((blockIdx.x * blockDim.x + threadIdx.x) >> 5);
    int lane = threadIdx.x & 31;
    if (gw >= n) return;
    int beg = g_offs[gw], end = g_offs[gw + 1];

    float adst[8], cv[8];
    #pragma unroll
    for (int h = 0; h < 8; h++) { adst[h] = g_Adst[(size_t)gw * 8 + h]; cv[h] = g_c[h]; }

    // pass 1: per-head max over incoming edges
    float mx[8];
    #pragma unroll
    for (int h = 0; h < 8; h++) mx[h] = -3.0e38f;
    for (int j = beg + lane; j < end; j += 32) {
        int s = g_srcs[j];
        float p = g_Pe[j], dt = g_De[j];
        const float* as = g_Asrc + (size_t)s * 8;
        #pragma unroll
        for (int h = 0; h < 8; h++) {
            float l = adst[h] + as[h] + p * cv[h] + dt;
            l = (l >= 0.f) ? l : 0.2f * l;
            mx[h] = fmaxf(mx[h], l);
        }
    }
    #pragma unroll
    for (int h = 0; h < 8; h++)
        #pragma unroll
        for (int o = 16; o; o >>= 1)
            mx[h] = fmaxf(mx[h], __shfl_xor_sync(0xffffffffu, mx[h], o));

    // pass 2: exp + sum, cache exp (minimal MUFU count)
    float sm8[8];
    #pragma unroll
    for (int h = 0; h < 8; h++) sm8[h] = 0.f;
    for (int j = beg + lane; j < end; j += 32) {
        int s = g_srcs[j];
        float p = g_Pe[j], dt = g_De[j];
        const float* as = g_Asrc + (size_t)s * 8;
        float ex[8];
        #pragma unroll
        for (int h = 0; h < 8; h++) {
            float l = adst[h] + as[h] + p * cv[h] + dt;
            l = (l >= 0.f) ? l : 0.2f * l;
            ex[h] = __expf(l - mx[h]);
            sm8[h] += ex[h];
        }
        *(float4*)(g_exp + (size_t)j * 8)     = make_float4(ex[0], ex[1], ex[2], ex[3]);
        *(float4*)(g_exp + (size_t)j * 8 + 4) = make_float4(ex[4], ex[5], ex[6], ex[7]);
    }
    #pragma unroll
    for (int h = 0; h < 8; h++)
        #pragma unroll
        for (int o = 16; o; o >>= 1)
            sm8[h] += __shfl_xor_sync(0xffffffffu, sm8[h], o);

    // pass 3: weighted aggregation; lane covers dims [lane*4, lane*4+4), head = lane>>2
    int h = lane >> 2;
    float dsel = (h & 4) ? ((h & 2) ? ((h & 1) ? sm8[7] : sm8[6]) : ((h & 1) ? sm8[5] : sm8[4]))
                         : ((h & 2) ? ((h & 1) ? sm8[3] : sm8[2]) : ((h & 1) ? sm8[1] : sm8[0]));
    float ri = __fdividef(1.0f, dsel + 1e-12f);

    float4 acc = make_float4(0.f, 0.f, 0.f, 0.f);
    const float4* Vv = (const float4*)g_V;
    for (int j = beg; j < end; j++) {
        float a = g_exp[(size_t)j * 8 + h] * ri;
        int s = g_srcs[j];
        float4 v = Vv[(size_t)s * 32 + lane];
        acc.x = fmaf(a, v.x, acc.x);
        acc.y = fmaf(a, v.y, acc.y);
        acc.z = fmaf(a, v.z, acc.z);
        acc.w = fmaf(a, v.w, acc.w);
    }
    *(float4*)(g_agg + (size_t)gw * DD + lane * 4) = acc;
}

// ---------------- out = LN(agg@Wout^T + Wout_b + R), epilogue in registers -------
__global__ void __launch_bounds__(256) k_out(const float* __restrict__ Wout,
                                             const float* __restrict__ Woutb,
                                             const float* __restrict__ lng,
                                             const float* __restrict__ lnb,
                                             float* __restrict__ out, int n) {
    __shared__ float As[128 * CPITCH];
    __shared__ float Ws[128 * CPITCH];
    int m0 = blockIdx.x * 128;
    int tid = threadIdx.x, tx = tid & 15, ty = tid >> 4;

    float acc[8][8];
    #pragma unroll
    for (int i = 0; i < 8; i++)
        #pragma unroll
        for (int j = 0; j < 8; j++) acc[i][j] = 0.f;
    for (int kc = 0; kc < 4; kc++) {
        load_chunk(As, g_agg, m0, n, kc);
        load_chunk(Ws, Wout, 0, 128, kc);
        __syncthreads();
        gemm_chunk(As, Ws, acc, tx, ty);
        __syncthreads();
    }

    // per-column constants for this thread's 8 output columns
    float wb[8], gv[8], bv[8];
    #pragma unroll
    for (int j = 0; j < 8; j++) {
        int col = tx + 16 * j;
        wb[j] = Woutb[col];
        gv[j] = lng[col];
        bv[j] = lnb[col];
    }

    // epilogue: bias + residual + LayerNorm per row.
    // Row (ty+16i) lives in the 16 threads sharing ty; those are lanes [0..15]
    // or [16..31] of a warp, so xor-shuffles with offsets 1/2/4/8 reduce within them.
    #pragma unroll
    for (int i = 0; i < 8; i++) {
        int grow = m0 + ty + 16 * i;
        float v[8];
        float s = 0.f, q = 0.f;
        #pragma unroll
        for (int j = 0; j < 8; j++) {
            float t = acc[i][j] + wb[j];
            if (grow < n) t += g_R[(size_t)grow * DD + tx + 16 * j];
            v[j] = t;
            s += t;
            q = fmaf(t, t, q);
        }
        #pragma unroll
        for (int o = 8; o; o >>= 1) {
            s += __shfl_xor_sync(0xffffffffu, s, o);
            q += __shfl_xor_sync(0xffffffffu, q, o);
        }
        float mu  = s * (1.0f / 128.0f);
        float var = q * (1.0f / 128.0f) - mu * mu;
        float inv = rsqrtf(var + 1e-5f);
        if (grow < n) {
            #pragma unroll
            for (int j = 0; j < 8; j++)
                out[(size_t)grow * DD + tx + 16 * j] = (v[j] - mu) * inv * gv[j] + bv[j];
        }
    }
}

// ---------------- launcher ----------------
extern "C" void kernel_launch(void* const* d_in, const int* in_sizes, int n_in,
                              void* d_out, int out_size) {
    const float* H     = (const float*)d_in[0];
    const int*   EI    = (const int*)d_in[1];     // int32! (JAX x64 disabled)
    const float* P     = (const float*)d_in[2];
    const float* DT    = (const float*)d_in[3];
    const float* W1    = (const float*)d_in[4];
    const float* W2    = (const float*)d_in[5];
    const float* W3    = (const float*)d_in[6];
    const float* W4    = (const float*)d_in[7];
    const float* Wv    = (const float*)d_in[8];
    const float* Woutw = (const float*)d_in[9];
    const float* Woutb = (const float*)d_in[10];
    const float* resw  = (const float*)d_in[11];
    const float* resb  = (const float*)d_in[12];
    const float* lng   = (const float*)d_in[13];
    const float* lnb   = (const float*)d_in[14];
    float* out = (float*)d_out;

    int n = in_sizes[0] / DD;   // 50000
    int e = in_sizes[2];        // 800000

    k_zero<<<(n + 255) / 256, 256>>>(n);
    k_prep<<<8, 256>>>(W1, W2, W3, W4);
    k_hist<<<(e + 255) / 256, 256>>>(EI, e, n);
    k_scan<<<1, 1024>>>(n);
    k_scatter<<<(e + 255) / 256, 256>>>(EI, P, DT, e, n);
    k_nodeproj<<<(n + 127) / 128, 256>>>(H, Wv, resw, resb, n);
    k_attn<<<(n + 7) / 8, 256>>>(n);
    k_out<<<(n + 127) / 128, 256>>>(Woutw, Woutb, lng, lnb, out, n);
}